// round 13
// baseline (speedup 1.0000x reference)
#include <cuda_runtime.h>
#include <cstdint>
#include <cstddef>

// Problem constants
#define D_HID 1024
#define N_SLOT 16
#define N_B 512
#define N_T 256
#define ATT_SCALE 0.03125f   // 1/sqrt(1024)

// ------------------- device scratch (no runtime allocation allowed) -------------------
__device__ __align__(16) float g_query[N_SLOT * D_HID];          // latent @ Wq^T + bq
__device__ __align__(16) float g_qt[N_SLOT * D_HID];             // scale * (query @ Wk)
__device__ __align__(16) float g_cvec[N_SLOT];                   // scale * query . bk
__device__ __align__(16) float g_M[D_HID * D_HID];               // Wo @ Wv (tf32-rounded)
__device__ __align__(16) float g_bp[D_HID];                      // Wo @ bv + bo
__device__ __align__(16) float g_Z[(size_t)N_B * N_SLOT * D_HID];// attn @ X (tf32-rounded)

// ------------------- helpers -------------------
__device__ __forceinline__ float warp_sum(float v) {
#pragma unroll
    for (int o = 16; o; o >>= 1) v += __shfl_xor_sync(0xffffffffu, v, o);
    return v;
}
__device__ __forceinline__ float to_tf32(float x) {
    uint32_t u;
    asm("cvt.rna.tf32.f32 %0, %1;" : "=r"(u) : "f"(x));
    return __uint_as_float(u);
}
// m16n8k8 tf32 mma, fp32 accumulate.  Fragment maps (validated in earlier rounds):
//   g = lane>>2, tg = lane&3
//   a0=A(g,tg) a1=A(g+8,tg) a2=A(g,tg+4) a3=A(g+8,tg+4)
//   b0=B(tg,g) b1=B(tg+4,g)            (B indexed as B(k,n))
//   d0=D(g,2tg) d1=D(g,2tg+1) d2=D(g+8,2tg) d3=D(g+8,2tg+1)
__device__ __forceinline__ void mma8(float c[4], const float a[4], const float b[2]) {
    asm volatile(
        "mma.sync.aligned.m16n8k8.row.col.f32.tf32.tf32.f32 "
        "{%0,%1,%2,%3},{%4,%5,%6,%7},{%8,%9},{%0,%1,%2,%3};\n"
        : "+f"(c[0]), "+f"(c[1]), "+f"(c[2]), "+f"(c[3])
        : "r"(__float_as_uint(a[0])), "r"(__float_as_uint(a[1])),
          "r"(__float_as_uint(a[2])), "r"(__float_as_uint(a[3])),
          "r"(__float_as_uint(b[0])), "r"(__float_as_uint(b[1])));
}
__device__ __forceinline__ void cp16(float* dst_smem, const float* src) {
    uint32_t d = (uint32_t)__cvta_generic_to_shared(dst_smem);
    asm volatile("cp.async.cg.shared.global [%0], [%1], 16;" :: "r"(d), "l"(src));
}
#define CP_COMMIT()  asm volatile("cp.async.commit_group;")
#define CP_WAIT2()   asm volatile("cp.async.wait_group 2;")
#define CP_WAIT1()   asm volatile("cp.async.wait_group 1;")
#define CP_WAIT0()   asm volatile("cp.async.wait_group 0;")

// X smem swizzle: element (r, c) at  r*1024 + (c ^ xf(r)),  xf(r) = 8*(r&3) | 4*((r>>2)&1).
// Conflict-free for BOTH the score-phase (fixed row) and Z-phase (fixed col) fragment loads,
// and preserves 16B contiguity for cp.async (xf multiple of 4).
__device__ __forceinline__ int xrow(int r) {
    return ((r & 3) << 3) | (((r >> 2) & 1) << 2);
}

// ------------------- tiny precompute kernels -------------------

// query[s,e] = dot(latent[s,:], Wq[e,:]) + bq[e].  One warp per output.
__global__ void __launch_bounds__(256) k_query(
    const float* __restrict__ latent, const float* __restrict__ Wq,
    const float* __restrict__ bq, float* __restrict__ outq)
{
    int w = (blockIdx.x * 256 + threadIdx.x) >> 5;   // 0..16383
    int lane = threadIdx.x & 31;
    int s = w >> 10, e = w & 1023;
    const float* l = latent + s * D_HID;
    const float* wr = Wq + (size_t)e * D_HID;
    float acc = 0.f;
#pragma unroll 8
    for (int k = lane; k < D_HID; k += 32) acc += l[k] * wr[k];
    acc = warp_sum(acc);
    if (lane == 0) outq[s * D_HID + e] = acc + bq[e];
}

// qt[s,d] = scale * sum_e query[s,e] * Wk[e,d].
// e-reduction split 2-way across the block (grid 128 = 16 s x 8 d-blocks).
__global__ void __launch_bounds__(256) k_qt(
    const float* __restrict__ query, const float* __restrict__ Wk,
    float* __restrict__ qt)
{
    __shared__ float red[128];
    int s = blockIdx.x >> 3;              // 0..15
    int dblk = blockIdx.x & 7;            // 0..7
    int dl = threadIdx.x & 127;
    int half = threadIdx.x >> 7;          // 0/1 -> e in [half*512, half*512+512)
    int d = dblk * 128 + dl;
    const float* q = query + s * D_HID + half * 512;
    const float* wp = Wk + (size_t)(half * 512) * D_HID + d;
    float a[8];
#pragma unroll
    for (int u = 0; u < 8; u++) a[u] = 0.f;
    for (int e = 0; e < 512; e += 8) {
#pragma unroll
        for (int u = 0; u < 8; u++)
            a[u] += q[e + u] * wp[(size_t)(e + u) * D_HID];
    }
    float r = ((a[0] + a[1]) + (a[2] + a[3])) + ((a[4] + a[5]) + (a[6] + a[7]));
    if (half) red[dl] = r;
    __syncthreads();
    if (!half) qt[s * D_HID + d] = (r + red[dl]) * ATT_SCALE;
}

// cvec[s] = scale * dot(query[s,:], bk)
__global__ void k_cvec(const float* __restrict__ query, const float* __restrict__ bk,
                       float* __restrict__ cvec)
{
    int w = threadIdx.x >> 5, lane = threadIdx.x & 31;
    if (w < N_SLOT) {
        const float* q = query + w * D_HID;
        float acc = 0.f;
#pragma unroll 8
        for (int k = lane; k < D_HID; k += 32) acc += q[k] * bk[k];
        acc = warp_sum(acc);
        if (lane == 0) cvec[w] = acc * ATT_SCALE;
    }
}

// bp[e] = dot(Wo[e,:], bv) + bo[e]
__global__ void __launch_bounds__(256) k_bp(
    const float* __restrict__ Wo, const float* __restrict__ bv,
    const float* __restrict__ bo, float* __restrict__ bp)
{
    int w = (blockIdx.x * 256 + threadIdx.x) >> 5;   // 0..1023
    int lane = threadIdx.x & 31;
    const float* wr = Wo + (size_t)w * D_HID;
    float acc = 0.f;
#pragma unroll 8
    for (int k = lane; k < D_HID; k += 32) acc += wr[k] * bv[k];
    acc = warp_sum(acc);
    if (lane == 0) bp[w] = acc + bo[w];
}

// ------------------- M = tf32(Wo @ Wv): 64x64x32 tiles, 256 thr, grid 256 -------------------
// v2: 8 warps/CTA (2m x 4n, warp tile 32x16) -> 13.8 warps/SM (was 6.8) for latency cover.
// B stored [k][n] pad-72 (bank = 8*tg+g bijective); A pad-36 (bank = 4*g+tg bijective).
#define MG_ASTG (64 * 36)                 // 2304 floats
#define MG_BSTG (32 * 72)                 // 2304 floats
#define MGEMM_SMEM_FLOATS (3 * (MG_ASTG + MG_BSTG))   // 13824 floats = 55296 B

__global__ void __launch_bounds__(256) k_gemm_m(
    const float* __restrict__ A, const float* __restrict__ B, float* __restrict__ C)
{
    extern __shared__ float smg[];
    const int tid = threadIdx.x;
    const int warp = tid >> 5, lane = tid & 31;
    const int g = lane >> 2, tg = lane & 3;
    const int wm = (warp >> 2) * 32;      // 0 / 32
    const int wn = (warp & 3) * 16;       // 0,16,32,48
    const int bm = blockIdx.y * 64, bn = blockIdx.x * 64;

    float acc[2][2][4];
#pragma unroll
    for (int mf = 0; mf < 2; mf++)
#pragma unroll
        for (int nf = 0; nf < 2; nf++)
#pragma unroll
            for (int r = 0; r < 4; r++) acc[mf][nf][r] = 0.f;

    auto load_stage = [&](int stage, int k0) {
        float* Asb = smg + stage * (MG_ASTG + MG_BSTG);
        float* Bsb = Asb + MG_ASTG;
#pragma unroll
        for (int i = 0; i < 2; i++) {
            int e = tid + i * 256;            // float4 idx 0..511
            int r = e >> 3, q = e & 7;
            cp16(&Asb[r * 36 + q * 4], A + (size_t)(bm + r) * D_HID + k0 + q * 4);
        }
#pragma unroll
        for (int i = 0; i < 2; i++) {
            int e = tid + i * 256;
            int r = e >> 4, q = e & 15;       // r = k row (32), q = n/4 (16)
            cp16(&Bsb[r * 72 + q * 4], B + (size_t)(k0 + r) * D_HID + bn + q * 4);
        }
        CP_COMMIT();
    };

    load_stage(0, 0);
    load_stage(1, 32);

    for (int it = 0; it < 32; it++) {
        if (it + 2 < 32) { load_stage((it + 2) % 3, (it + 2) * 32); CP_WAIT2(); }
        else if (it + 1 < 32) { CP_WAIT1(); }
        else { CP_WAIT0(); }
        __syncthreads();
        const float* Asv = smg + (it % 3) * (MG_ASTG + MG_BSTG);
        const float* Bsv = Asv + MG_ASTG;

#pragma unroll
        for (int k8 = 0; k8 < 32; k8 += 8) {
            float a[2][4];
#pragma unroll
            for (int mf = 0; mf < 2; mf++) {
                int r = wm + mf * 16;
                a[mf][0] = to_tf32(Asv[(r + g) * 36 + k8 + tg]);
                a[mf][1] = to_tf32(Asv[(r + g + 8) * 36 + k8 + tg]);
                a[mf][2] = to_tf32(Asv[(r + g) * 36 + k8 + tg + 4]);
                a[mf][3] = to_tf32(Asv[(r + g + 8) * 36 + k8 + tg + 4]);
            }
            float bf[2][2];
#pragma unroll
            for (int nf = 0; nf < 2; nf++) {
                int n0 = wn + nf * 8;
                bf[nf][0] = to_tf32(Bsv[(k8 + tg) * 72 + n0 + g]);
                bf[nf][1] = to_tf32(Bsv[(k8 + tg + 4) * 72 + n0 + g]);
            }
#pragma unroll
            for (int mf = 0; mf < 2; mf++)
#pragma unroll
                for (int nf = 0; nf < 2; nf++)
                    mma8(acc[mf][nf], a[mf], bf[nf]);
        }
        __syncthreads();
    }

#pragma unroll
    for (int mf = 0; mf < 2; mf++) {
#pragma unroll
        for (int nf = 0; nf < 2; nf++) {
            int row = bm + wm + mf * 16 + g;
            int col = bn + wn + nf * 8 + tg * 2;
            C[(size_t)row * D_HID + col]           = to_tf32(acc[mf][nf][0]);
            C[(size_t)row * D_HID + col + 1]       = to_tf32(acc[mf][nf][1]);
            C[(size_t)(row + 8) * D_HID + col]     = to_tf32(acc[mf][nf][2]);
            C[(size_t)(row + 8) * D_HID + col + 1] = to_tf32(acc[mf][nf][3]);
        }
    }
}

// ------------------- fused attention: scores + softmax (no max shift) + Z -------------------
// CTA per batch. t-tiles of 16, full d=1024 per tile in smem (swizzled).
// v4: THREE X buffers with 2-tile-deep cp.async prefetch (128KB in flight) so each tile's
// wait covers two loads.  Trailing sync retained: prefetch target (it+2)%3 aliases the
// buffer read in iter it-1; that sync orders the reuse.
#define SM_XS   0                          // 3 x 16 x 1024
#define SM_SP   (3 * 16 * 1024)            // 8 x 16 x 17
#define SM_PS   (SM_SP + 8 * 16 * 17)      // 16 x 20
#define SM_LG   (SM_PS + 16 * 20)          // 256
#define SM_CV   (SM_LG + 256)              // 16
#define SM_LS   (SM_CV + 16)               // 16
#define ATTN_SMEM_FLOATS (SM_LS + 16)      // 51952 floats = 207808 B

__global__ void __launch_bounds__(256) k_attn(
    const float* __restrict__ X, const float* __restrict__ logits,
    const float* __restrict__ qt, const float* __restrict__ cvec,
    float* __restrict__ Z)
{
    extern __shared__ float sm[];
    float* Sp = sm + SM_SP;
    float* Ps = sm + SM_PS;
    float* Lg = sm + SM_LG;
    float* Cv = sm + SM_CV;
    float* Ls = sm + SM_LS;

    const int b = blockIdx.x;
    const int tid = threadIdx.x;
    const int w = tid >> 5, lane = tid & 31;
    const int g = lane >> 2, tg = lane & 3;
    const int xfg = xrow(g);                 // xrow(g) == xrow(g+8)
    const float* Xb = X + (size_t)b * (N_T * D_HID);

    // preload qt A-fragments (warp w owns d in [w*128, w*128+128)), tf32-rounded
    float qa[16][4];
#pragma unroll
    for (int j = 0; j < 16; j++) {
        int d0 = w * 128 + j * 8;
        qa[j][0] = to_tf32(qt[g * D_HID + d0 + tg]);
        qa[j][1] = to_tf32(qt[(g + 8) * D_HID + d0 + tg]);
        qa[j][2] = to_tf32(qt[g * D_HID + d0 + tg + 4]);
        qa[j][3] = to_tf32(qt[(g + 8) * D_HID + d0 + tg + 4]);
    }
    float zc[16][4];
#pragma unroll
    for (int nf = 0; nf < 16; nf++) {
        zc[nf][0] = 0.f; zc[nf][1] = 0.f; zc[nf][2] = 0.f; zc[nf][3] = 0.f;
    }
    Lg[tid] = logits[b * N_T + tid];
    if (tid < 16) { Cv[tid] = cvec[tid]; Ls[tid] = 0.f; }

    // prologue: async-load tiles 0 and 1 (swizzled dest), one commit group each
#pragma unroll
    for (int t0 = 0; t0 < 2; t0++) {
        float* Xd = sm + SM_XS + t0 * (16 * 1024);
        const float* Xg = Xb + (size_t)t0 * 16 * D_HID;
#pragma unroll
        for (int i = 0; i < 16; i++) {
            int e = tid + i * 256;               // float4 idx 0..4095
            int r = e >> 8, c4 = e & 255;
            cp16(&Xd[r * 1024 + ((c4 * 4) ^ xrow(r))], Xg + (size_t)r * D_HID + c4 * 4);
        }
        CP_COMMIT();
    }

    for (int it = 0; it < 16; it++) {
        float* Xs = sm + SM_XS + (it % 3) * (16 * 1024);
        if (it + 2 < 16) {
            float* Xn = sm + SM_XS + ((it + 2) % 3) * (16 * 1024);
            const float* Xg = Xb + (size_t)(it + 2) * 16 * D_HID;
#pragma unroll
            for (int i = 0; i < 16; i++) {
                int e = tid + i * 256;
                int r = e >> 8, c4 = e & 255;
                cp16(&Xn[r * 1024 + ((c4 * 4) ^ xrow(r))],
                     Xg + (size_t)r * D_HID + c4 * 4);
            }
            CP_COMMIT();
            CP_WAIT2();
        } else if (it + 1 < 16) {
            CP_WAIT1();
        } else {
            CP_WAIT0();
        }
        __syncthreads();

        // scores partials: warp w sums its d-range; cvt at load (== pre-rounding X)
        float sc0[4] = {0.f, 0.f, 0.f, 0.f}, sc1[4] = {0.f, 0.f, 0.f, 0.f};
        const int rowlo = g * 1024, rowhi = (g + 8) * 1024;
#pragma unroll
        for (int j = 0; j < 16; j++) {
            int d0 = w * 128 + j * 8;
            int c0 = (d0 + tg) ^ xfg, c1 = (d0 + tg + 4) ^ xfg;
            float bf0[2], bf1[2];
            bf0[0] = to_tf32(Xs[rowlo + c0]);
            bf0[1] = to_tf32(Xs[rowlo + c1]);
            bf1[0] = to_tf32(Xs[rowhi + c0]);
            bf1[1] = to_tf32(Xs[rowhi + c1]);
            mma8(sc0, qa[j], bf0);
            mma8(sc1, qa[j], bf1);
        }
        float* spw = Sp + w * (16 * 17);
        spw[g * 17 + tg * 2]               = sc0[0];
        spw[g * 17 + tg * 2 + 1]           = sc0[1];
        spw[(g + 8) * 17 + tg * 2]         = sc0[2];
        spw[(g + 8) * 17 + tg * 2 + 1]     = sc0[3];
        spw[g * 17 + 8 + tg * 2]           = sc1[0];
        spw[g * 17 + 8 + tg * 2 + 1]       = sc1[1];
        spw[(g + 8) * 17 + 8 + tg * 2]     = sc1[2];
        spw[(g + 8) * 17 + 8 + tg * 2 + 1] = sc1[3];
        __syncthreads();

        // reduce partials + softmax numerator (no max shift), thread per element
        {
            int s = tid >> 4, t = tid & 15;
            float v = 0.f;
#pragma unroll
            for (int ww = 0; ww < 8; ww++) v += Sp[ww * (16 * 17) + s * 17 + t];
            v += Cv[s] + Lg[it * 16 + t];
            float p = to_tf32(__expf(v));    // round BEFORE summing: bias cancels in Z/L
            float ps = p;
#pragma unroll
            for (int o = 8; o; o >>= 1) ps += __shfl_xor_sync(0xffffffffu, ps, o, 16);
            Ps[s * 20 + t] = p;
            if (t == 0) Ls[s] += ps;
        }
        __syncthreads();

        // Z-mma over this tile (Xs re-read as B(k=t, n=d); conflict-free via swizzle)
#pragma unroll
        for (int k0 = 0; k0 < 16; k0 += 8) {
            float pa[4];
            pa[0] = Ps[g * 20 + k0 + tg];
            pa[1] = Ps[(g + 8) * 20 + k0 + tg];
            pa[2] = Ps[g * 20 + k0 + tg + 4];
            pa[3] = Ps[(g + 8) * 20 + k0 + tg + 4];
            const int r1 = (k0 + tg) * 1024, r2 = (k0 + tg + 4) * 1024;
            const int xz1 = tg << 3, xz2 = (tg << 3) | 4;
#pragma unroll
            for (int nf = 0; nf < 16; nf++) {
                int n0 = w * 128 + nf * 8;
                float bf[2];
                bf[0] = to_tf32(Xs[r1 + ((n0 + g) ^ xz1)]);
                bf[1] = to_tf32(Xs[r2 + ((n0 + g) ^ xz2)]);
                mma8(zc[nf], pa, bf);
            }
        }
        __syncthreads();   // orders buffer reuse for the (it+2)%3 prefetch target
    }

    // epilogue: normalize and store Z (tf32-rounded so the out-GEMM truncation is exact)
    float inv_lo = 1.f / Ls[g], inv_hi = 1.f / Ls[g + 8];
    float* Zb = Z + (size_t)b * (N_SLOT * D_HID);
#pragma unroll
    for (int nf = 0; nf < 16; nf++) {
        int n0 = w * 128 + nf * 8 + tg * 2;
        Zb[g * D_HID + n0]           = to_tf32(zc[nf][0] * inv_lo);
        Zb[g * D_HID + n0 + 1]       = to_tf32(zc[nf][1] * inv_lo);
        Zb[(g + 8) * D_HID + n0]     = to_tf32(zc[nf][2] * inv_hi);
        Zb[(g + 8) * D_HID + n0 + 1] = to_tf32(zc[nf][3] * inv_hi);
    }
}

// ------------------- TF32 GEMM v3: 128x128x32, 256 thr, 3-stage cp.async -------------------
// out = Z @ M^T + bp.  B given as [N][K] row-major.  minBlocks=2 guarantees 2 CTAs/SM
// (regs <= 128; smem 2x110.6KB = 221KB <= 228KB) so latency is covered by a co-resident CTA.
#define GSTG 4608                      // floats per stage buffer (128*36)
#define GEMM_SMEM_FLOATS (6 * GSTG)    // 110592 B

__global__ void __launch_bounds__(256, 2) k_gemm3(
    const float* __restrict__ A, const float* __restrict__ B,
    const float* __restrict__ bias, float* __restrict__ C,
    int Md, int Nd, int Kd)
{
    extern __shared__ float smg[];

    const int tid = threadIdx.x;
    const int warp = tid >> 5, lane = tid & 31;
    const int g = lane >> 2, tg = lane & 3;
    const int wm = (warp >> 2) * 64;   // 0 / 64
    const int wn = (warp & 3) * 32;    // 0,32,64,96
    const int bm = blockIdx.y * 128, bn = blockIdx.x * 128;

    float acc[4][4][4];
#pragma unroll
    for (int mf = 0; mf < 4; mf++)
#pragma unroll
        for (int nf = 0; nf < 4; nf++)
#pragma unroll
            for (int r = 0; r < 4; r++) acc[mf][nf][r] = 0.f;

    const int nIter = Kd >> 5;

    auto load_stage = [&](int stage, int k0) {
        float* Asb = smg + stage * GSTG;
        float* Bsb = smg + (3 + stage) * GSTG;
#pragma unroll
        for (int i = 0; i < 4; i++) {
            int e = tid + i * 256;          // float4 idx 0..1023
            int r = e >> 3, q = e & 7;
            cp16(&Asb[r * 36 + q * 4], A + (size_t)(bm + r) * Kd + k0 + q * 4);
        }
#pragma unroll
        for (int i = 0; i < 4; i++) {
            int e = tid + i * 256;
            int r = e >> 3, q = e & 7;      // r = n index
            cp16(&Bsb[r * 36 + q * 4], B + (size_t)(bn + r) * Kd + k0 + q * 4);
        }
        CP_COMMIT();
    };

    load_stage(0, 0);
    load_stage(1, 32);

    for (int it = 0; it < nIter; it++) {
        if (it + 2 < nIter) { load_stage((it + 2) % 3, (it + 2) * 32); CP_WAIT2(); }
        else if (it + 1 < nIter) { CP_WAIT1(); }
        else { CP_WAIT0(); }
        __syncthreads();

        const float* Asv = smg + (it % 3) * GSTG;
        const float* Bsv = smg + (3 + it % 3) * GSTG;

#pragma unroll
        for (int k8 = 0; k8 < 32; k8 += 8) {
            float a[4][4];
#pragma unroll
            for (int mf = 0; mf < 4; mf++) {
                int r = wm + mf * 16;
                a[mf][0] = Asv[(r + g) * 36 + k8 + tg];
                a[mf][1] = Asv[(r + g + 8) * 36 + k8 + tg];
                a[mf][2] = Asv[(r + g) * 36 + k8 + tg + 4];
                a[mf][3] = Asv[(r + g + 8) * 36 + k8 + tg + 4];
            }
            float bf[4][2];
#pragma unroll
            for (int nf = 0; nf < 4; nf++) {
                int n0 = wn + nf * 8;
                bf[nf][0] = Bsv[(n0 + g) * 36 + k8 + tg];
                bf[nf][1] = Bsv[(n0 + g) * 36 + k8 + tg + 4];
            }
#pragma unroll
            for (int mf = 0; mf < 4; mf++)
#pragma unroll
                for (int nf = 0; nf < 4; nf++)
                    mma8(acc[mf][nf], a[mf], bf[nf]);
        }
        __syncthreads();
    }

    // epilogue
#pragma unroll
    for (int mf = 0; mf < 4; mf++) {
#pragma unroll
        for (int nf = 0; nf < 4; nf++) {
            int row = bm + wm + mf * 16 + g;
            int col = bn + wn + nf * 8 + tg * 2;
            float b0 = bias[col];
            float b1 = bias[col + 1];
            C[(size_t)row * Nd + col]           = acc[mf][nf][0] + b0;
            C[(size_t)row * Nd + col + 1]       = acc[mf][nf][1] + b1;
            C[(size_t)(row + 8) * Nd + col]     = acc[mf][nf][2] + b0;
            C[(size_t)(row + 8) * Nd + col + 1] = acc[mf][nf][3] + b1;
        }
    }
}

// ------------------- launch -------------------
extern "C" void kernel_launch(void* const* d_in, const int* in_sizes, int n_in,
                              void* d_out, int out_size)
{
    const float* X      = (const float*)d_in[0];   // [512,256,1024]
    const float* logits = (const float*)d_in[1];   // [512,256]
    const float* latent = (const float*)d_in[2];   // [16,1024]
    const float* Wq = (const float*)d_in[3];
    const float* bq = (const float*)d_in[4];
    const float* Wk = (const float*)d_in[5];
    const float* bk = (const float*)d_in[6];
    const float* Wv = (const float*)d_in[7];
    const float* bv = (const float*)d_in[8];
    const float* Wo = (const float*)d_in[9];
    const float* bo = (const float*)d_in[10];
    float* out = (float*)d_out;                    // [512,16,1024]

    float *query, *qt, *cvec, *M, *bp, *Z;
    cudaGetSymbolAddress((void**)&query, g_query);
    cudaGetSymbolAddress((void**)&qt,    g_qt);
    cudaGetSymbolAddress((void**)&cvec,  g_cvec);
    cudaGetSymbolAddress((void**)&M,     g_M);
    cudaGetSymbolAddress((void**)&bp,    g_bp);
    cudaGetSymbolAddress((void**)&Z,     g_Z);

    const int attn_smem  = ATTN_SMEM_FLOATS * 4;    // 207808 B
    const int gemm_smem  = GEMM_SMEM_FLOATS * 4;    // 110592 B
    const int mgemm_smem = MGEMM_SMEM_FLOATS * 4;   // 55296 B
    cudaFuncSetAttribute(k_attn, cudaFuncAttributeMaxDynamicSharedMemorySize, attn_smem);
    cudaFuncSetAttribute(k_gemm3, cudaFuncAttributeMaxDynamicSharedMemorySize, gemm_smem);
    cudaFuncSetAttribute(k_gemm_m, cudaFuncAttributeMaxDynamicSharedMemorySize, mgemm_smem);

    // Order chosen so k_attn is launch #4 (the one ncu captures).
    // Deps: query -> {qt, cvec} -> attn -> gemm3; {gemm_m, bp} -> gemm3.  All serial-stream safe.
    k_query<<<2048, 256>>>(latent, Wq, bq, query);
    k_qt<<<128, 256>>>(query, Wk, qt);
    k_cvec<<<1, 512>>>(query, bk, cvec);
    k_attn<<<N_B, 256, attn_smem>>>(X, logits, qt, cvec, Z);
    k_gemm_m<<<dim3(16, 16), 256, mgemm_smem>>>(Wo, Wv, M);
    k_bp<<<128, 256>>>(Wo, bv, bo, bp);
    k_gemm3<<<dim3(D_HID / 128, (N_B * N_SLOT) / 128), 256, gemm_smem>>>(
        Z, M, bp, out, N_B * N_SLOT, D_HID, D_HID);
}